// round 7
// baseline (speedup 1.0000x reference)
#include <cuda_runtime.h>
#include <math.h>
#include <cstdint>

#define THREADS 128

typedef unsigned long long u64;
typedef unsigned int u32;

// ---------------- f32x2 helpers ----------------
__device__ __forceinline__ u64 ffma2(u64 a, u64 b, u64 c) {
    u64 d; asm("fma.rn.f32x2 %0, %1, %2, %3;" : "=l"(d) : "l"(a), "l"(b), "l"(c)); return d;
}
__device__ __forceinline__ u64 mul2(u64 a, u64 b) {
    u64 d; asm("mul.rn.f32x2 %0, %1, %2;" : "=l"(d) : "l"(a), "l"(b)); return d;
}
__device__ __forceinline__ u64 dup2(float x) {
    u64 d; unsigned u = __float_as_uint(x);
    asm("mov.b64 %0, {%1, %2};" : "=l"(d) : "r"(u), "r"(u)); return d;
}
__device__ __forceinline__ u64 pack2(float a, float b) {
    u64 d; asm("mov.b64 %0, {%1, %2};" : "=l"(d) : "r"(__float_as_uint(a)), "r"(__float_as_uint(b))); return d;
}
__device__ __forceinline__ void unpack2(u64 v, float &lo, float &hi) {
    unsigned a, b; asm("mov.b64 {%0, %1}, %2;" : "=r"(a), "=r"(b) : "l"(v));
    lo = __uint_as_float(a); hi = __uint_as_float(b);
}
__device__ __forceinline__ u32 f2tf32(float f) {
    u32 r; asm("cvt.rna.tf32.f32 %0, %1;" : "=r"(r) : "f"(f)); return r;
}

// mma.sync m16n8k8 tf32 (portable sm_80+ path; runs on tensor pipe)
__device__ __forceinline__ void mma8r(float* acc, u32 a0, u32 a1, u32 a2, u32 a3, u64 b) {
    u32 b0 = (u32)b, b1 = (u32)(b >> 32);
    asm volatile("mma.sync.aligned.m16n8k8.row.col.f32.tf32.tf32.f32 "
                 "{%0,%1,%2,%3}, {%4,%5,%6,%7}, {%8,%9}, {%0,%1,%2,%3};"
                 : "+f"(acc[0]), "+f"(acc[1]), "+f"(acc[2]), "+f"(acc[3])
                 : "r"(a0), "r"(a1), "r"(a2), "r"(a3), "r"(b0), "r"(b1));
}

__device__ __forceinline__ float qredf(float v) {
    v += __shfl_xor_sync(0xffffffffu, v, 1);
    v += __shfl_xor_sync(0xffffffffu, v, 2);
    return v;
}

__device__ __forceinline__ float sel4(int t, float4 f) {
    return t == 0 ? f.x : (t == 1 ? f.y : (t == 2 ? f.z : f.w));
}

// ---------------- smem layout (bytes) ----------------
#define SM_Q     0        /* float4[128]                2048 */
#define SM_MP2   2048     /* ulonglong2[128] (H0,H1)    2048 */
#define SM_BQ    4096     /* u64[8][8][4]               2048 */
#define SM_BEXT  6144     /* u64[256][4]                8192 */
#define SM_A     16384    /* u32 tf32 [128][64] xor-swz 32768 */
#define SM_BP    49152    /* u64[8kk][256n][4tq]        65536 */
#define SMEM_BYTES 114688

#define LK_A 0.84852813742385703f  /* 0.6*sqrt(2) */
#define LK_B 0.56568542494923801f  /* 0.4*sqrt(2) */

__global__ __launch_bounds__(THREADS, 2)
void coupling_mma_kernel(const float* __restrict__ coords,
                         const float* __restrict__ c,
                         const float* __restrict__ Wx1, const float* __restrict__ bx1,
                         const float* __restrict__ Wx2, const float* __restrict__ bx2,
                         const float* __restrict__ Wy1, const float* __restrict__ by1,
                         const float* __restrict__ Wy2, const float* __restrict__ by2,
                         float* __restrict__ out, long M)
{
    extern __shared__ char smem[];
    const int tid  = threadIdx.x;
    const int lane = tid & 31;
    const int warp = tid >> 5;
    const int g    = lane >> 2;     // 0..7
    const int tq   = lane & 3;      // 0..3
    const long base = (long)blockIdx.x * 128;

    const float s1 = 1.0f / sqrtf(68.0f);
    const float s2 = 1.0f / sqrtf(192.0f);

    float4* QS = (float4*)(smem + SM_Q);
    ulonglong2* MP2 = (ulonglong2*)(smem + SM_MP2);
    u64*    BQ = (u64*)(smem + SM_BQ);
    u64*    BEXT = (u64*)(smem + SM_BEXT);
    u32*    AS = (u32*)(smem + SM_A);
    u64*    BP = (u64*)(smem + SM_BP);

    // ---------- staging ----------
    // A: c[128 x 64] -> tf32 bits, layout row*64 + (k ^ ((row&7)<<2))
    #pragma unroll
    for (int i = 0; i < 16; i++) {
        int idx = tid + i * THREADS;          // float4 index
        int row = idx >> 4;
        int k4  = (idx & 15) << 2;
        long gr = base + row;
        float4 v = make_float4(0.f, 0.f, 0.f, 0.f);
        if (gr < M) v = *(const float4*)(c + gr * 64 + k4);
        uint4 tv = { f2tf32(v.x), f2tf32(v.y), f2tf32(v.z), f2tf32(v.w) };
        *(uint4*)(AS + row * 64 + (k4 ^ ((row & 7) << 2))) = tv;
    }
    // Bpack [kk][n][tq]: (W[n][kk*8+tq], W[n][kk*8+tq+4]) prescaled, tf32.
    // Linear addressing in the hot loop; banks structurally conflict-free.
    #pragma unroll
    for (int i = 0; i < 64; i++) {
        int idx = tid + i * THREADS;          // 0..8191
        int t  = idx & 3;
        int n  = (idx >> 2) & 255;
        int kk = idx >> 10;
        const float* Wg = (n < 128) ? Wx1 : Wy1;
        int row = n & 127;
        int k0 = kk * 8 + t;
        u32 lo = f2tf32(Wg[row * 68 + 4 + k0] * s1);
        u32 hi = f2tf32(Wg[row * 68 + 4 + k0 + 4] * s1);
        BP[idx] = ((u64)hi << 32) | lo;
    }
    // BEXT [n][tq]: (W1s[tq][n], tq==0 ? b1[n] : 0)
    #pragma unroll
    for (int i = 0; i < 8; i++) {
        int idx = tid + i * THREADS;          // 0..1023
        int n = idx >> 2;
        int t = idx & 3;
        const float* Wg  = (n < 128) ? Wx1 : Wy1;
        const float* b1g = (n < 128) ? bx1 : by1;
        int row = n & 127;
        u32 lo = f2tf32(Wg[row * 68 + t] * s1);
        u32 hi = (t == 0) ? f2tf32(b1g[row]) : 0u;
        BEXT[idx] = ((u64)hi << 32) | lo;
    }
    // BQ [kk][n][tq]: q-GEMM weights. col n: 0=qx0,1=qx1,2=qy0,3=qy1, 4..7 zero.
    #pragma unroll
    for (int i = 0; i < 2; i++) {
        int idx = tid + i * THREADS;          // 0..255
        int t  = idx & 3;
        int n  = (idx >> 2) & 7;
        int kk = idx >> 5;
        u64 v = 0;
        if (n < 4) {
            const float* Wsrc = (n >> 1) ? Wy2 : Wx2;
            int ob = (n & 1) * 192 + 128;
            u32 lo = f2tf32(Wsrc[ob + kk * 8 + t] * s2);
            u32 hi = f2tf32(Wsrc[ob + kk * 8 + t + 4] * s2);
            v = ((u64)hi << 32) | lo;
        }
        BQ[idx] = v;
    }
    // MP2: jp -> (H0, H1)
    {
        int jp = tid;
        int j0 = 2 * jp;
        int st = j0 >> 7;
        int jj0 = j0 & 127, jj1 = jj0 + 1;
        const float* W2g = st ? Wy2 : Wx2;
        ulonglong2 p;
        p.x = pack2(W2g[jj0] * s2, W2g[jj1] * s2);
        p.y = pack2(W2g[192 + jj0] * s2, W2g[192 + jj1] * s2);
        MP2[jp] = p;
    }
    __syncthreads();

    // ---------- A fragments (cached, reused for q-GEMM and both stages) ----------
    u32 afr[2][8][4];
    {
        const int swz = g << 2;   // rows used always have row&7 == g
        #pragma unroll
        for (int mt = 0; mt < 2; mt++) {
            int r0 = warp * 32 + mt * 16 + g;
            #pragma unroll
            for (int kk = 0; kk < 8; kk++) {
                int k0 = kk * 8 + tq;
                afr[mt][kk][0] = AS[r0 * 64 + (k0 ^ swz)];
                afr[mt][kk][1] = AS[(r0 + 8) * 64 + (k0 ^ swz)];
                afr[mt][kk][2] = AS[r0 * 64 + ((k0 + 4) ^ swz)];
                afr[mt][kk][3] = AS[(r0 + 8) * 64 + ((k0 + 4) ^ swz)];
            }
        }
    }

    // ---------- q-GEMM: q[rows, 4] = c @ W2c^T (tensor core) ----------
    {
        float aq[2][4];
        #pragma unroll
        for (int mt = 0; mt < 2; mt++)
            #pragma unroll
            for (int q = 0; q < 4; q++) aq[mt][q] = 0.0f;
        const u64* bq = BQ + g * 4 + tq;
        #pragma unroll
        for (int kk = 0; kk < 8; kk++) {
            u64 b = bq[kk * 32];
            mma8r(aq[0], afr[0][kk][0], afr[0][kk][1], afr[0][kk][2], afr[0][kk][3], b);
            mma8r(aq[1], afr[1][kk][0], afr[1][kk][1], afr[1][kk][2], afr[1][kk][3], b);
        }
        // C frag: (row g | g+8, cols 2tq, 2tq+1). tq=0 -> (qx0,qx1), tq=1 -> (qy0,qy1).
        if (tq < 2) {
            float b0 = tq ? by2[0] : bx2[0];
            float b1 = tq ? by2[1] : bx2[1];
            #pragma unroll
            for (int mt = 0; mt < 2; mt++) {
                int r0 = warp * 32 + mt * 16 + g;
                *(u64*)((float*)&QS[r0]     + tq * 2) = pack2(aq[mt][0] + b0, aq[mt][1] + b1);
                *(u64*)((float*)&QS[r0 + 8] + tq * 2) = pack2(aq[mt][2] + b0, aq[mt][3] + b1);
            }
        }
    }
    __syncwarp();

    // rows owned by this thread (quad-redundant)
    int R[4];
    #pragma unroll
    for (int ri = 0; ri < 4; ri++) R[ri] = warp * 32 + ri * 8 + g;

    float cin[4], cup[4], lsum[4];
    #pragma unroll
    for (int ri = 0; ri < 4; ri++) {
        long rr = base + R[ri];
        float2 xy = make_float2(0.f, 0.f);
        if (rr < M) xy = ((const float2*)coords)[rr];
        cin[ri] = xy.x; cup[ri] = xy.y; lsum[ri] = 0.0f;
    }

    const u64 lkA = dup2(LK_A), lkB = dup2(LK_B);
    const u64 ABSM = 0x7FFFFFFF7FFFFFFFull;
    const u32 eone = (tq == 0) ? 0x3F800000u : 0u;  // feat[tq+4] = (k==4 -> 1)
    const u64* bpt = BP + g * 4 + tq;               // hot-loop base (linear addressing)
    const u64* bet = BEXT + g * 4 + tq;

    for (int st = 0; st < 2; st++) {
        // per-row sin features (registers; quad-uniform inputs)
        float4 fs[4];
        #pragma unroll
        for (int ri = 0; ri < 4; ri++) {
            float a = cin[ri] * 0.1f, sa, ca;
            sincosf(a, &sa, &ca);
            fs[ri] = make_float4(sa, 2.0f * sa * ca, ca, 1.0f - 2.0f * sa * sa);
        }
        // extension A fragment per m-tile
        u32 e0[2], e1[2];
        #pragma unroll
        for (int mt = 0; mt < 2; mt++) {
            e0[mt] = f2tf32(sel4(tq, fs[2 * mt]));
            e1[mt] = f2tf32(sel4(tq, fs[2 * mt + 1]));
        }

        u64 po0[4], po1[4];
        #pragma unroll
        for (int ri = 0; ri < 4; ri++) { po0[ri] = pack2(0.f, 0.f); po1[ri] = po0[ri]; }

        for (int chunk = 0; chunk < 4; chunk++) {
            int nbase = st * 16 + chunk * 4;       // n-tile index
            float acc[2][4][4];
            #pragma unroll
            for (int mt = 0; mt < 2; mt++)
                #pragma unroll
                for (int nt = 0; nt < 4; nt++)
                    #pragma unroll
                    for (int q = 0; q < 4; q++) acc[mt][nt][q] = 0.0f;

            // extension step first (starts the acc chains)
            #pragma unroll
            for (int nt = 0; nt < 4; nt++) {
                u64 be = bet[(nbase + nt) * 32];
                mma8r(acc[0][nt], e0[0], e1[0], eone, eone, be);
                mma8r(acc[1][nt], e0[1], e1[1], eone, eone, be);
            }

            #pragma unroll
            for (int kk = 0; kk < 8; kk++) {
                u64 bfr[4];
                #pragma unroll
                for (int nt = 0; nt < 4; nt++)
                    bfr[nt] = bpt[kk * 1024 + (nbase + nt) * 32];
                #pragma unroll
                for (int nt = 0; nt < 4; nt++) {
                    mma8r(acc[0][nt], afr[0][kk][0], afr[0][kk][1], afr[0][kk][2], afr[0][kk][3], bfr[nt]);
                    mma8r(acc[1][nt], afr[1][kk][0], afr[1][kk][1], afr[1][kk][2], afr[1][kk][3], bfr[nt]);
                }
            }

            // epilogue: leaky + dot into o partials (bias+sin already in acc)
            #pragma unroll
            for (int nt = 0; nt < 4; nt++) {
                int jp = st * 64 + chunk * 16 + nt * 4 + tq;
                ulonglong2 P = MP2[jp];
                u64 H0 = P.x, H1 = P.y;
                #pragma unroll
                for (int mt = 0; mt < 2; mt++) {
                    #pragma unroll
                    for (int h = 0; h < 2; h++) {
                        int ri = mt * 2 + h;
                        u64 v = pack2(acc[mt][nt][2 * h + 0], acc[mt][nt][2 * h + 1]);
                        u64 av = v & ABSM;
                        u64 hh = ffma2(lkA, v, mul2(lkB, av));
                        po0[ri] = ffma2(hh, H0, po0[ri]);
                        po1[ri] = ffma2(hh, H1, po1[ri]);
                    }
                }
            }
        }

        // reduce + coordinate update
        #pragma unroll
        for (int ri = 0; ri < 4; ri++) {
            float a0, a1, b0, b1;
            unpack2(po0[ri], a0, a1);
            unpack2(po1[ri], b0, b1);
            float o0 = qredf(a0 + a1);
            float o1 = qredf(b0 + b1);
            float4 qv = QS[R[ri]];
            o0 += st ? qv.z : qv.x;
            o1 += st ? qv.w : qv.y;
            float ls = fminf(fmaxf(o0, -5.0f), 5.0f);
            float up_new = cup[ri] * __expf(ls) + o1;
            lsum[ri] += ls;
            cup[ri] = cin[ri];
            cin[ri] = up_new;
        }
    }

    // after stage 1: cin = x_final, cup = y_final. tq==0 lanes store directly.
    if (tq == 0) {
        #pragma unroll
        for (int ri = 0; ri < 4; ri++) {
            long rr = base + R[ri];
            if (rr < M) {
                ((float2*)out)[rr] = make_float2(cin[ri], cup[ri]);
                out[2 * M + rr] = lsum[ri];
            }
        }
    }
}

extern "C" void kernel_launch(void* const* d_in, const int* in_sizes, int n_in,
                              void* d_out, int out_size) {
    const float* coords = (const float*)d_in[0];
    const float* c      = (const float*)d_in[1];
    const float* Wx1    = (const float*)d_in[2];
    const float* bx1    = (const float*)d_in[3];
    const float* Wx2    = (const float*)d_in[4];
    const float* bx2    = (const float*)d_in[5];
    const float* Wy1    = (const float*)d_in[6];
    const float* by1    = (const float*)d_in[7];
    const float* Wy2    = (const float*)d_in[8];
    const float* by2    = (const float*)d_in[9];
    float* out = (float*)d_out;

    long M = (long)in_sizes[1] / 64;
    int grid = (int)((M + 127) / 128);

    cudaFuncSetAttribute(coupling_mma_kernel,
                         cudaFuncAttributeMaxDynamicSharedMemorySize, SMEM_BYTES);
    coupling_mma_kernel<<<grid, THREADS, SMEM_BYTES>>>(coords, c,
                                                       Wx1, bx1, Wx2, bx2,
                                                       Wy1, by1, Wy2, by2,
                                                       out, M);
}

// round 8
// speedup vs baseline: 1.1647x; 1.1647x over previous
#include <cuda_runtime.h>
#include <math.h>
#include <cstdint>

#define THREADS 128

typedef unsigned long long u64;
typedef unsigned int u32;

// ---------------- f32x2 helpers ----------------
__device__ __forceinline__ u64 ffma2(u64 a, u64 b, u64 c) {
    u64 d; asm("fma.rn.f32x2 %0, %1, %2, %3;" : "=l"(d) : "l"(a), "l"(b), "l"(c)); return d;
}
__device__ __forceinline__ u64 mul2(u64 a, u64 b) {
    u64 d; asm("mul.rn.f32x2 %0, %1, %2;" : "=l"(d) : "l"(a), "l"(b)); return d;
}
__device__ __forceinline__ u64 dup2(float x) {
    u64 d; unsigned u = __float_as_uint(x);
    asm("mov.b64 %0, {%1, %2};" : "=l"(d) : "r"(u), "r"(u)); return d;
}
__device__ __forceinline__ u64 pack2(float a, float b) {
    u64 d; asm("mov.b64 %0, {%1, %2};" : "=l"(d) : "r"(__float_as_uint(a)), "r"(__float_as_uint(b))); return d;
}
__device__ __forceinline__ void unpack2(u64 v, float &lo, float &hi) {
    unsigned a, b; asm("mov.b64 {%0, %1}, %2;" : "=r"(a), "=r"(b) : "l"(v));
    lo = __uint_as_float(a); hi = __uint_as_float(b);
}
__device__ __forceinline__ u64 packu(u32 lo, u32 hi) {
    u64 d; asm("mov.b64 %0, {%1, %2};" : "=l"(d) : "r"(lo), "r"(hi)); return d;
}
__device__ __forceinline__ u32 f2tf32(float f) {
    u32 r; asm("cvt.rna.tf32.f32 %0, %1;" : "=r"(r) : "f"(f)); return r;
}

// mma.sync m16n8k8 tf32 (portable sm_80+ path; runs on tensor pipe)
__device__ __forceinline__ void mma8r(float* acc, u32 a0, u32 a1, u32 a2, u32 a3, u64 b) {
    u32 b0 = (u32)b, b1 = (u32)(b >> 32);
    asm volatile("mma.sync.aligned.m16n8k8.row.col.f32.tf32.tf32.f32 "
                 "{%0,%1,%2,%3}, {%4,%5,%6,%7}, {%8,%9}, {%0,%1,%2,%3};"
                 : "+f"(acc[0]), "+f"(acc[1]), "+f"(acc[2]), "+f"(acc[3])
                 : "r"(a0), "r"(a1), "r"(a2), "r"(a3), "r"(b0), "r"(b1));
}

__device__ __forceinline__ float qredf(float v) {
    v += __shfl_xor_sync(0xffffffffu, v, 1);
    v += __shfl_xor_sync(0xffffffffu, v, 2);
    return v;
}

__device__ __forceinline__ float sel4(int t, float4 f) {
    return t == 0 ? f.x : (t == 1 ? f.y : (t == 2 ? f.z : f.w));
}

// ---------------- smem layout (bytes) — fits 3 CTAs/SM ----------------
#define SM_QS    0        /* float4[128]                       2048 */
#define SM_MP2   2048     /* ulonglong2[128] (H0,H1)           2048 */
#define SM_BQ    4096     /* u64[8kk][4n][4tq]                 1024 */
#define SM_BEXTL 5120     /* u32[256n][4tq]                    4096 */
#define SM_BEXTB 9216     /* u32[256n] bias plane              1024 */
#define SM_AB1   10240    /* 32768: A tile, then BP1 (stage-y) */
#define SM_BP0   43008    /* u64[8kk][128n][4tq] stage-x       32768 */
#define SMEM_BYTES 75776

#define LK_A 0.84852813742385703f  /* 0.6*sqrt(2) */
#define LK_B 0.56568542494923801f  /* 0.4*sqrt(2) */

__global__ __launch_bounds__(THREADS, 3)
void coupling_mma_kernel(const float* __restrict__ coords,
                         const float* __restrict__ c,
                         const float* __restrict__ Wx1, const float* __restrict__ bx1,
                         const float* __restrict__ Wx2, const float* __restrict__ bx2,
                         const float* __restrict__ Wy1, const float* __restrict__ by1,
                         const float* __restrict__ Wy2, const float* __restrict__ by2,
                         float* __restrict__ out, long M)
{
    extern __shared__ char smem[];
    const int tid  = threadIdx.x;
    const int lane = tid & 31;
    const int warp = tid >> 5;
    const int g    = lane >> 2;     // 0..7
    const int tq   = lane & 3;      // 0..3
    const long base = (long)blockIdx.x * 128;

    const float s1 = 1.0f / sqrtf(68.0f);
    const float s2 = 1.0f / sqrtf(192.0f);

    float4* QS = (float4*)(smem + SM_QS);
    ulonglong2* MP2 = (ulonglong2*)(smem + SM_MP2);
    u64*  BQ    = (u64*)(smem + SM_BQ);
    u32*  BEXTL = (u32*)(smem + SM_BEXTL);
    u32*  BEXTB = (u32*)(smem + SM_BEXTB);
    u32*  AS    = (u32*)(smem + SM_AB1);
    u64*  BP1   = (u64*)(smem + SM_AB1);
    u64*  BP0   = (u64*)(smem + SM_BP0);

    // ---------- staging ----------
    // A: c[128 x 64] -> tf32 bits, layout row*64 + (k ^ ((row&7)<<2))
    #pragma unroll
    for (int i = 0; i < 16; i++) {
        int idx = tid + i * THREADS;          // float4 index
        int row = idx >> 4;
        int k4  = (idx & 15) << 2;
        long gr = base + row;
        float4 v = make_float4(0.f, 0.f, 0.f, 0.f);
        if (gr < M) v = *(const float4*)(c + gr * 64 + k4);
        uint4 tv = { f2tf32(v.x), f2tf32(v.y), f2tf32(v.z), f2tf32(v.w) };
        *(uint4*)(AS + row * 64 + (k4 ^ ((row & 7) << 2))) = tv;
    }
    // BP0 [kk][128][4]: stage-x weights (Wx1), linear addressing in hot loop
    #pragma unroll
    for (int i = 0; i < 32; i++) {
        int idx = tid + i * THREADS;          // 0..4095
        int t  = idx & 3;
        int n  = (idx >> 2) & 127;
        int kk = idx >> 9;
        int k0 = kk * 8 + t;
        u32 lo = f2tf32(Wx1[n * 68 + 4 + k0] * s1);
        u32 hi = f2tf32(Wx1[n * 68 + 4 + k0 + 4] * s1);
        BP0[idx] = packu(lo, hi);
    }
    // BEXTL [n][tq] = W1s[tq][n] (lo plane);  BEXTB [n] = b1[n] (bias plane)
    #pragma unroll
    for (int i = 0; i < 8; i++) {
        int idx = tid + i * THREADS;          // 0..1023
        int n = idx >> 2;
        int t = idx & 3;
        const float* Wg = (n < 128) ? Wx1 : Wy1;
        BEXTL[idx] = f2tf32(Wg[(n & 127) * 68 + t] * s1);
    }
    #pragma unroll
    for (int i = 0; i < 2; i++) {
        int n = tid + i * THREADS;            // 0..255
        const float* b1g = (n < 128) ? bx1 : by1;
        BEXTB[n] = f2tf32(b1g[n & 127]);
    }
    // BQ [kk][4][4]: q-GEMM weights. col n: 0=qx0,1=qx1,2=qy0,3=qy1
    if (tid < 128) {
        int t  = tid & 3;
        int n  = (tid >> 2) & 3;
        int kk = tid >> 4;
        const float* Wsrc = (n >> 1) ? Wy2 : Wx2;
        int ob = (n & 1) * 192 + 128;
        u32 lo = f2tf32(Wsrc[ob + kk * 8 + t] * s2);
        u32 hi = f2tf32(Wsrc[ob + kk * 8 + t + 4] * s2);
        BQ[tid] = packu(lo, hi);
    }
    // MP2: jp -> (H0, H1)
    {
        int jp = tid;
        int j0 = 2 * jp;
        int st = j0 >> 7;
        int jj0 = j0 & 127, jj1 = jj0 + 1;
        const float* W2g = st ? Wy2 : Wx2;
        ulonglong2 p;
        p.x = pack2(W2g[jj0] * s2, W2g[jj1] * s2);
        p.y = pack2(W2g[192 + jj0] * s2, W2g[192 + jj1] * s2);
        MP2[jp] = p;
    }
    __syncthreads();

    // ---------- A fragments (cached; A smem dies after this) ----------
    u32 afr[2][8][4];
    {
        const int swz = g << 2;   // rows used always have row&7 == g
        #pragma unroll
        for (int mt = 0; mt < 2; mt++) {
            int r0 = warp * 32 + mt * 16 + g;
            #pragma unroll
            for (int kk = 0; kk < 8; kk++) {
                int k0 = kk * 8 + tq;
                afr[mt][kk][0] = AS[r0 * 64 + (k0 ^ swz)];
                afr[mt][kk][1] = AS[(r0 + 8) * 64 + (k0 ^ swz)];
                afr[mt][kk][2] = AS[r0 * 64 + ((k0 + 4) ^ swz)];
                afr[mt][kk][3] = AS[(r0 + 8) * 64 + ((k0 + 4) ^ swz)];
            }
        }
    }

    // ---------- q-GEMM: q[rows, 4] = c @ W2c^T (tensor core) ----------
    {
        float aq[2][4];
        #pragma unroll
        for (int mt = 0; mt < 2; mt++)
            #pragma unroll
            for (int q = 0; q < 4; q++) aq[mt][q] = 0.0f;
        const u64* bq = BQ + (g & 3) * 4 + tq;   // lanes g>=4 alias cols 0-3 (unused outputs)
        #pragma unroll
        for (int kk = 0; kk < 8; kk++) {
            u64 b = bq[kk * 16];
            mma8r(aq[0], afr[0][kk][0], afr[0][kk][1], afr[0][kk][2], afr[0][kk][3], b);
            mma8r(aq[1], afr[1][kk][0], afr[1][kk][1], afr[1][kk][2], afr[1][kk][3], b);
        }
        // C frag: (rows r0|r0+8, cols 2tq,2tq+1). tq=0 -> (qx0,qx1), tq=1 -> (qy0,qy1).
        if (tq < 2) {
            float b0 = tq ? by2[0] : bx2[0];
            float b1 = tq ? by2[1] : bx2[1];
            #pragma unroll
            for (int mt = 0; mt < 2; mt++) {
                int r0 = warp * 32 + mt * 16 + g;
                *(u64*)((float*)&QS[r0]     + tq * 2) = pack2(aq[mt][0] + b0, aq[mt][1] + b1);
                *(u64*)((float*)&QS[r0 + 8] + tq * 2) = pack2(aq[mt][2] + b0, aq[mt][3] + b1);
            }
        }
    }
    __syncthreads();   // all afr loaded; A region may now be overwritten

    // ---------- restage: BP1 [kk][128][4] = stage-y weights (Wy1) over A ----------
    #pragma unroll
    for (int i = 0; i < 32; i++) {
        int idx = tid + i * THREADS;          // 0..4095
        int t  = idx & 3;
        int n  = (idx >> 2) & 127;
        int kk = idx >> 9;
        int k0 = kk * 8 + t;
        u32 lo = f2tf32(Wy1[n * 68 + 4 + k0] * s1);
        u32 hi = f2tf32(Wy1[n * 68 + 4 + k0 + 4] * s1);
        BP1[idx] = packu(lo, hi);
    }

    // rows owned by this thread (quad-redundant)
    int R[4];
    #pragma unroll
    for (int ri = 0; ri < 4; ri++) R[ri] = warp * 32 + ri * 8 + g;

    float cin[4], cup[4], lsum[4];
    #pragma unroll
    for (int ri = 0; ri < 4; ri++) {
        long rr = base + R[ri];
        float2 xy = make_float2(0.f, 0.f);
        if (rr < M) xy = ((const float2*)coords)[rr];
        cin[ri] = xy.x; cup[ri] = xy.y; lsum[ri] = 0.0f;
    }

    const u64 lkA = dup2(LK_A), lkB = dup2(LK_B);
    const u64 ABSM = 0x7FFFFFFF7FFFFFFFull;
    const u32 eone = (tq == 0) ? 0x3F800000u : 0u;  // feat[k=4] = 1 (bias column)
    const u64* bp0t = BP0 + g * 4 + tq;
    const u64* bp1t = BP1 + g * 4 + tq;
    const u32* belt = BEXTL + g * 4 + tq;
    const u32* bebt = BEXTB + g;

    for (int st = 0; st < 2; st++) {
        if (st == 1) __syncthreads();   // BP1 stores visible before stage-1 reads

        const u64* bpt = st ? bp1t : bp0t;
        const int noff = st * 128;      // BEXT plane offset

        // per-row sin features (registers; quad-uniform inputs)
        float4 fs[4];
        #pragma unroll
        for (int ri = 0; ri < 4; ri++) {
            float a = cin[ri] * 0.1f, sa, ca;
            sincosf(a, &sa, &ca);
            fs[ri] = make_float4(sa, 2.0f * sa * ca, ca, 1.0f - 2.0f * sa * sa);
        }
        u32 e0[2], e1[2];
        #pragma unroll
        for (int mt = 0; mt < 2; mt++) {
            e0[mt] = f2tf32(sel4(tq, fs[2 * mt]));
            e1[mt] = f2tf32(sel4(tq, fs[2 * mt + 1]));
        }

        u64 po0[4], po1[4];
        #pragma unroll
        for (int ri = 0; ri < 4; ri++) { po0[ri] = pack2(0.f, 0.f); po1[ri] = po0[ri]; }

        for (int chunk = 0; chunk < 4; chunk++) {
            int nbase = chunk * 4;                // n-tile within stage (0..15)
            float acc[2][4][4];
            #pragma unroll
            for (int mt = 0; mt < 2; mt++)
                #pragma unroll
                for (int nt = 0; nt < 4; nt++)
                    #pragma unroll
                    for (int q = 0; q < 4; q++) acc[mt][nt][q] = 0.0f;

            // K-extension step (sin features + bias) starts the acc chains
            #pragma unroll
            for (int nt = 0; nt < 4; nt++) {
                int nb = (nbase + nt) * 8;
                u32 lo = belt[(noff + nb) * 4];
                u32 hi = (tq == 0) ? bebt[noff + nb] : 0u;
                u64 be = packu(lo, hi);
                mma8r(acc[0][nt], e0[0], e1[0], eone, eone, be);
                mma8r(acc[1][nt], e0[1], e1[1], eone, eone, be);
            }

            #pragma unroll
            for (int kk = 0; kk < 8; kk++) {
                u64 bfr[4];
                #pragma unroll
                for (int nt = 0; nt < 4; nt++)
                    bfr[nt] = bpt[kk * 512 + (nbase + nt) * 32];
                #pragma unroll
                for (int nt = 0; nt < 4; nt++) {
                    mma8r(acc[0][nt], afr[0][kk][0], afr[0][kk][1], afr[0][kk][2], afr[0][kk][3], bfr[nt]);
                    mma8r(acc[1][nt], afr[1][kk][0], afr[1][kk][1], afr[1][kk][2], afr[1][kk][3], bfr[nt]);
                }
            }

            // epilogue: leaky + dot into o partials (bias+sin already in acc)
            #pragma unroll
            for (int nt = 0; nt < 4; nt++) {
                int jp = st * 64 + chunk * 16 + nt * 4 + tq;
                ulonglong2 P = MP2[jp];
                u64 H0 = P.x, H1 = P.y;
                #pragma unroll
                for (int mt = 0; mt < 2; mt++) {
                    #pragma unroll
                    for (int h = 0; h < 2; h++) {
                        int ri = mt * 2 + h;
                        u64 v = pack2(acc[mt][nt][2 * h + 0], acc[mt][nt][2 * h + 1]);
                        u64 av = v & ABSM;
                        u64 hh = ffma2(lkA, v, mul2(lkB, av));
                        po0[ri] = ffma2(hh, H0, po0[ri]);
                        po1[ri] = ffma2(hh, H1, po1[ri]);
                    }
                }
            }
        }

        // reduce + coordinate update
        #pragma unroll
        for (int ri = 0; ri < 4; ri++) {
            float a0, a1, b0, b1;
            unpack2(po0[ri], a0, a1);
            unpack2(po1[ri], b0, b1);
            float o0 = qredf(a0 + a1);
            float o1 = qredf(b0 + b1);
            float4 qv = QS[R[ri]];
            o0 += st ? qv.z : qv.x;
            o1 += st ? qv.w : qv.y;
            float ls = fminf(fmaxf(o0, -5.0f), 5.0f);
            float up_new = cup[ri] * __expf(ls) + o1;
            lsum[ri] += ls;
            cup[ri] = cin[ri];
            cin[ri] = up_new;
        }
    }

    // after stage 1: cin = x_final, cup = y_final. tq==0 lanes store directly.
    if (tq == 0) {
        #pragma unroll
        for (int ri = 0; ri < 4; ri++) {
            long rr = base + R[ri];
            if (rr < M) {
                ((float2*)out)[rr] = make_float2(cin[ri], cup[ri]);
                out[2 * M + rr] = lsum[ri];
            }
        }
    }
}

extern "C" void kernel_launch(void* const* d_in, const int* in_sizes, int n_in,
                              void* d_out, int out_size) {
    const float* coords = (const float*)d_in[0];
    const float* c      = (const float*)d_in[1];
    const float* Wx1    = (const float*)d_in[2];
    const float* bx1    = (const float*)d_in[3];
    const float* Wx2    = (const float*)d_in[4];
    const float* bx2    = (const float*)d_in[5];
    const float* Wy1    = (const float*)d_in[6];
    const float* by1    = (const float*)d_in[7];
    const float* Wy2    = (const float*)d_in[8];
    const float* by2    = (const float*)d_in[9];
    float* out = (float*)d_out;

    long M = (long)in_sizes[1] / 64;
    int grid = (int)((M + 127) / 128);

    cudaFuncSetAttribute(coupling_mma_kernel,
                         cudaFuncAttributeMaxDynamicSharedMemorySize, SMEM_BYTES);
    coupling_mma_kernel<<<grid, THREADS, SMEM_BYTES>>>(coords, c,
                                                       Wx1, bx1, Wx2, bx2,
                                                       Wy1, by1, Wy2, by2,
                                                       out, M);
}